// round 2
// baseline (speedup 1.0000x reference)
#include <cuda_runtime.h>
#include <cuda_bf16.h>

#define Bn 256
#define Ln 1024
#define En 128
#define Hn 256
#define Vn 64

// ---- device-global scratch (no allocations allowed) ----
__device__ float g_proj[Vn * Hn];                    // token -> x_proj row (b_e folded in)
__device__ float g_hout[(size_t)Bn * Ln * Hn];       // all hidden states, 268MB
__device__ int   g_x_is32;

// ---------------- dtype detection ----------------
__global__ void k_reset() { g_x_is32 = 0; }

__global__ void k_detect(const unsigned int* __restrict__ xw) {
    int i = blockIdx.x * blockDim.x + threadIdx.x;
    int idx = 2 * i + 1;                 // odd 32-bit words
    if (idx < Bn * Ln) {
        if (xw[idx] != 0u) g_x_is32 = 1; // int64 high halves are all zero (vals 0..63)
    }
}

// ---------------- projection table ----------------
// proj[v][h] = sum_e emb[v][e] * W_e[h][e] + b_e[h]
__global__ void k_proj(const float* __restrict__ emb, const float* __restrict__ We,
                       const float* __restrict__ be) {
    __shared__ float es[En];
    int v = blockIdx.x, j = threadIdx.x;
    if (j < En) es[j] = emb[v * En + j];
    __syncthreads();
    float acc = 0.f;
    #pragma unroll
    for (int e = 0; e < En; e++) acc = fmaf(es[e], We[j * En + e], acc);
    g_proj[v * Hn + j] = acc + be[j];
}

__device__ __forceinline__ float bf_lo(unsigned int w) { return __uint_as_float(w << 16); }
__device__ __forceinline__ float bf_hi(unsigned int w) { return __uint_as_float(w & 0xffff0000u); }

// ---------------- recurrence ----------------
// 128 CTAs x 256 threads. CTA owns batches (2c, 2c+1) for the full 1024-step chain.
// W_h lives in smem as bf16 pairs: Wp[q][j] = {W[j][4q..4q+3]} packed 2x bf16x2.
// Thread j computes output element j for both batches.
#define RNN_SMEM (131072 + 4096)

__global__ void __launch_bounds__(256, 1) k_rnn(const void* __restrict__ xraw,
        const float* __restrict__ hidden, const float* __restrict__ Wh,
        const float* __restrict__ bh, float* __restrict__ dout, int write_final) {
    extern __shared__ char smem[];
    uint2* Wp = (uint2*)smem;                 // [64][256] uint2 = 128KB
    float* hs = (float*)(smem + 131072);      // [2 buf][2 batch][256]
    const int j  = threadIdx.x;
    const int b0 = 2 * blockIdx.x, b1 = b0 + 1;
    const int is32 = g_x_is32;
    const int* x32       = (const int*)xraw;
    const long long* x64 = (const long long*)xraw;

    // pack W_h -> bf16 smem, conflict-free stores
    for (int p = j; p < 64 * 256; p += 256) {
        int jj = p & 255, q = p >> 8;
        const float4 w4 = *(const float4*)(Wh + jj * Hn + 4 * q);
        __nv_bfloat162 lo2 = __floats2bfloat162_rn(w4.x, w4.y);
        __nv_bfloat162 hi2 = __floats2bfloat162_rn(w4.z, w4.w);
        uint2 u;
        u.x = *(unsigned int*)&lo2;
        u.y = *(unsigned int*)&hi2;
        Wp[q * 256 + jj] = u;
    }
    hs[j]       = hidden[b0 * Hn + j];
    hs[256 + j] = hidden[b1 * Hn + j];
    const float bhj = bh[j];
    __syncthreads();

    float fin0 = 0.f, fin1 = 0.f;
    for (int t = 0; t < Ln; t++) {
        const int cur = t & 1;
        // prefetch token + x_proj early (overlaps matvec)
        int tok0 = is32 ? x32[b0 * Ln + t] : (int)x64[b0 * Ln + t];
        int tok1 = is32 ? x32[b1 * Ln + t] : (int)x64[b1 * Ln + t];
        float xp0 = g_proj[tok0 * Hn + j];
        float xp1 = g_proj[tok1 * Hn + j];

        const float4* h0 = (const float4*)(hs + cur * 512);
        const float4* h1 = (const float4*)(hs + cur * 512 + 256);
        float a0 = 0.f, a1 = 0.f, c0 = 0.f, c1 = 0.f;
        #pragma unroll 16
        for (int q = 0; q < 64; q++) {
            uint2 w = Wp[q * 256 + j];            // my row chunk (conflict-free)
            float4 ha = h0[q];                    // broadcast
            float4 hb = h1[q];                    // broadcast
            float w0 = bf_lo(w.x), w1 = bf_hi(w.x);
            float w2 = bf_lo(w.y), w3 = bf_hi(w.y);
            a0 = fmaf(w0, ha.x, a0); c0 = fmaf(w1, ha.y, c0);
            a0 = fmaf(w2, ha.z, a0); c0 = fmaf(w3, ha.w, c0);
            a1 = fmaf(w0, hb.x, a1); c1 = fmaf(w1, hb.y, c1);
            a1 = fmaf(w2, hb.z, a1); c1 = fmaf(w3, hb.w, c1);
        }
        float nh0 = tanhf(a0 + c0 + xp0 + bhj);
        float nh1 = tanhf(a1 + c1 + xp1 + bhj);
        g_hout[((size_t)b0 * Ln + t) * Hn + j] = nh0;
        g_hout[((size_t)b1 * Ln + t) * Hn + j] = nh1;
        const int nxt = cur ^ 1;
        hs[nxt * 512 + j]       = nh0;
        hs[nxt * 512 + 256 + j] = nh1;
        fin0 = nh0; fin1 = nh1;
        __syncthreads();
    }
    if (write_final) {
        dout[(size_t)Bn * Ln * Vn + b0 * Hn + j] = fin0;
        dout[(size_t)Bn * Ln * Vn + b1 * Hn + j] = fin1;
    }
}

// ---------------- logits GEMM ----------------
// logits[r][v] = sum_k hout[r][k] * fcw[v][k] + fcb[v]
// Persistent grid; fcw^T resident in smem; 64-row tiles; 4x4 register blocking.
#define LOG_SMEM (65536 + 64 * 260 * 4)

__global__ void __launch_bounds__(256, 1) k_logits(const float* __restrict__ fcw,
        const float* __restrict__ fcb, float* __restrict__ out) {
    extern __shared__ char smem[];
    float* fT  = (float*)smem;              // [256][64]  fT[k][v] = fcw[v][k]
    float* hsm = (float*)(smem + 65536);    // [64][260]
    const int tid = threadIdx.x;
    const int tx = tid & 15, ty = tid >> 4;

    for (int p = tid; p < Vn * Hn; p += 256) {   // conflict-free transposed fill
        int v = p & 63, k = p >> 6;
        fT[k * 64 + v] = fcw[v * Hn + k];
    }
    float4 bias = *(const float4*)(fcb + 4 * tx);
    __syncthreads();

    const int ntiles = (Bn * Ln) / 64;      // 4096
    for (int tile = blockIdx.x; tile < ntiles; tile += gridDim.x) {
        const float4* src = (const float4*)(g_hout + (size_t)tile * 64 * Hn);
        for (int p = tid; p < 64 * 64; p += 256) {
            int row = p >> 6, kc = p & 63;
            *(float4*)(hsm + row * 260 + 4 * kc) = src[p];
        }
        __syncthreads();

        float acc[4][4];
        #pragma unroll
        for (int r = 0; r < 4; r++)
            #pragma unroll
            for (int c = 0; c < 4; c++) acc[r][c] = 0.f;

        #pragma unroll 8
        for (int k = 0; k < Hn; k++) {
            float4 b4 = *(const float4*)(fT + k * 64 + 4 * tx);
            float a0 = hsm[(4 * ty + 0) * 260 + k];
            float a1 = hsm[(4 * ty + 1) * 260 + k];
            float a2 = hsm[(4 * ty + 2) * 260 + k];
            float a3 = hsm[(4 * ty + 3) * 260 + k];
            acc[0][0] = fmaf(a0, b4.x, acc[0][0]); acc[0][1] = fmaf(a0, b4.y, acc[0][1]);
            acc[0][2] = fmaf(a0, b4.z, acc[0][2]); acc[0][3] = fmaf(a0, b4.w, acc[0][3]);
            acc[1][0] = fmaf(a1, b4.x, acc[1][0]); acc[1][1] = fmaf(a1, b4.y, acc[1][1]);
            acc[1][2] = fmaf(a1, b4.z, acc[1][2]); acc[1][3] = fmaf(a1, b4.w, acc[1][3]);
            acc[2][0] = fmaf(a2, b4.x, acc[2][0]); acc[2][1] = fmaf(a2, b4.y, acc[2][1]);
            acc[2][2] = fmaf(a2, b4.z, acc[2][2]); acc[2][3] = fmaf(a2, b4.w, acc[2][3]);
            acc[3][0] = fmaf(a3, b4.x, acc[3][0]); acc[3][1] = fmaf(a3, b4.y, acc[3][1]);
            acc[3][2] = fmaf(a3, b4.z, acc[3][2]); acc[3][3] = fmaf(a3, b4.w, acc[3][3]);
        }
        #pragma unroll
        for (int r = 0; r < 4; r++) {
            float4 o;
            o.x = acc[r][0] + bias.x; o.y = acc[r][1] + bias.y;
            o.z = acc[r][2] + bias.z; o.w = acc[r][3] + bias.w;
            *(float4*)(out + ((size_t)tile * 64 + 4 * ty + r) * 64 + 4 * tx) = o;
        }
        __syncthreads();
    }
}

// ---------------- launch ----------------
extern "C" void kernel_launch(void* const* d_in, const int* in_sizes, int n_in,
                              void* d_out, int out_size) {
    const void*  x      = d_in[0];
    const float* hidden = (const float*)d_in[1];
    const float* emb    = (const float*)d_in[2];
    const float* We     = (const float*)d_in[3];
    const float* be     = (const float*)d_in[4];
    const float* Wh     = (const float*)d_in[5];
    const float* bhp    = (const float*)d_in[6];
    const float* fcw    = (const float*)d_in[7];
    const float* fcb    = (const float*)d_in[8];
    float* out = (float*)d_out;

    cudaFuncSetAttribute(k_rnn,    cudaFuncAttributeMaxDynamicSharedMemorySize, RNN_SMEM);
    cudaFuncSetAttribute(k_logits, cudaFuncAttributeMaxDynamicSharedMemorySize, LOG_SMEM);

    k_reset<<<1, 1>>>();
    k_detect<<<(Bn * Ln / 2 + 255) / 256, 256>>>((const unsigned int*)x);
    k_proj<<<Vn, Hn>>>(emb, We, be);

    int write_final = (out_size >= Bn * Ln * Vn + Bn * Hn) ? 1 : 0;
    k_rnn<<<Bn / 2, Hn, RNN_SMEM>>>(x, hidden, Wh, bhp, out, write_final);
    k_logits<<<148, 256, LOG_SMEM>>>(fcw, fcb, out);
}